// round 1
// baseline (speedup 1.0000x reference)
#include <cuda_runtime.h>
#include <math.h>

#define N_NODES 100000
#define N_EDGES 640000

// ---------------- scratch (device globals; no allocation allowed) ----------
__device__ float g_agg[(size_t)N_NODES * 256];   // aggregation buffer (max K=256)
__device__ float g_h1 [(size_t)N_NODES * 256];   // layer1 output
__device__ float g_h2 [(size_t)N_NODES * 128];   // layer2 output
__device__ float g_invdeg[N_NODES];
__device__ int   g_deg[N_NODES];
__device__ int   g_is64;                          // edge_index dtype flag

// ---------------- edge access (int32 or int64 layout) ----------------------
__device__ __forceinline__ int edge_at(const void* p, long long i) {
    if (g_is64) return (int)((const long long*)p)[i];
    return ((const int*)p)[i];
}

// Detect int64 edge_index: if int64 (values < 2^31), every odd 32-bit word is 0.
__global__ void detect_kernel(const void* edges) {
    __shared__ int nz;
    if (threadIdx.x == 0) nz = 0;
    __syncthreads();
    const int* p = (const int*)edges;
    for (int i = threadIdx.x; i < 1024; i += blockDim.x) {
        if (p[2 * i + 1] != 0) atomicOr(&nz, 1);
    }
    __syncthreads();
    if (threadIdx.x == 0) g_is64 = (nz == 0) ? 1 : 0;
}

__global__ void count_kernel(const void* edges) {
    int e = blockIdx.x * blockDim.x + threadIdx.x;
    if (e < N_EDGES) {
        int d = edge_at(edges, (long long)N_EDGES + e);
        atomicAdd(&g_deg[d], 1);
    }
}

__global__ void invdeg_kernel() {
    int i = blockIdx.x * blockDim.x + threadIdx.x;
    if (i < N_NODES) {
        int d = g_deg[i];
        g_invdeg[i] = 1.0f / (float)(d > 1 ? d : 1);
    }
}

// ---------------- scatter-add: agg[dst] += feat[src] -----------------------
template <int K>
__global__ void scatter_kernel(const void* edges, const float* __restrict__ feat) {
    const int CPE = K / 4;                       // float4 chunks per edge
    int idx = blockIdx.x * blockDim.x + threadIdx.x;
    if (idx >= N_EDGES * CPE) return;
    int e = idx / CPE;
    int c = (idx % CPE) * 4;
    int s = edge_at(edges, e);
    int d = edge_at(edges, (long long)N_EDGES + e);
    float4 v = *(const float4*)(feat + (size_t)s * K + c);
    float* dst = g_agg + (size_t)d * K + c;
    atomicAdd(dst + 0, v.x);
    atomicAdd(dst + 1, v.y);
    atomicAdd(dst + 2, v.z);
    atomicAdd(dst + 3, v.w);
}

// ---------------- fused GEMM: C = (A1*invdeg)@W1^T + A2@W2^T + bias --------
// A1: [M,K1] (aggregation, scaled per-row by invdeg), A2: [M,K2]
// W1: [Nout,K1], W2: [Nout,K2]. Tile 64x64x16, 256 threads, 4x4 per thread.
__global__ void gemm_kernel(const float* __restrict__ A1, int K1,
                            const float* __restrict__ A2, int K2,
                            const float* __restrict__ W1,
                            const float* __restrict__ W2,
                            const float* __restrict__ bias,
                            float* __restrict__ C, int Nout) {
    const int M = N_NODES;
    __shared__ float As[16][68];
    __shared__ float Bs[16][68];

    int tid = threadIdx.x;
    int m0 = blockIdx.x * 64;
    int n0 = blockIdx.y * 64;

    int lrow = tid >> 2;          // 0..63 (m or n index within tile)
    int lk4  = (tid & 3) * 4;     // 0,4,8,12 (k within tile)
    int ty = tid >> 4;            // 0..15
    int tx = tid & 15;            // 0..15

    int am = m0 + lrow;
    float idg = (am < M) ? g_invdeg[am] : 0.0f;
    int bn = n0 + lrow;           // Nout is a multiple of 64; no guard needed

    float acc[4][4];
#pragma unroll
    for (int i = 0; i < 4; i++)
#pragma unroll
        for (int j = 0; j < 4; j++) acc[i][j] = 0.0f;

    int K = K1 + K2;
    for (int kt = 0; kt < K; kt += 16) {
        int kk = kt + lk4;
        // A tile (with invdeg fused into the agg half)
        float4 av = make_float4(0.f, 0.f, 0.f, 0.f);
        if (am < M) {
            if (kk < K1) {
                av = *(const float4*)(A1 + (size_t)am * K1 + kk);
                av.x *= idg; av.y *= idg; av.z *= idg; av.w *= idg;
            } else {
                av = *(const float4*)(A2 + (size_t)am * K2 + (kk - K1));
            }
        }
        As[lk4 + 0][lrow] = av.x;
        As[lk4 + 1][lrow] = av.y;
        As[lk4 + 2][lrow] = av.z;
        As[lk4 + 3][lrow] = av.w;
        // B tile
        float4 bv;
        if (kk < K1) bv = *(const float4*)(W1 + (size_t)bn * K1 + kk);
        else         bv = *(const float4*)(W2 + (size_t)bn * K2 + (kk - K1));
        Bs[lk4 + 0][lrow] = bv.x;
        Bs[lk4 + 1][lrow] = bv.y;
        Bs[lk4 + 2][lrow] = bv.z;
        Bs[lk4 + 3][lrow] = bv.w;
        __syncthreads();

#pragma unroll
        for (int k = 0; k < 16; k++) {
            float a[4], b[4];
#pragma unroll
            for (int i = 0; i < 4; i++) a[i] = As[k][ty * 4 + i];
#pragma unroll
            for (int j = 0; j < 4; j++) b[j] = Bs[k][tx * 4 + j];
#pragma unroll
            for (int i = 0; i < 4; i++)
#pragma unroll
                for (int j = 0; j < 4; j++) acc[i][j] += a[i] * b[j];
        }
        __syncthreads();
    }

#pragma unroll
    for (int i = 0; i < 4; i++) {
        int m = m0 + ty * 4 + i;
        if (m >= M) continue;
        float* crow = C + (size_t)m * Nout + n0 + tx * 4;
#pragma unroll
        for (int j = 0; j < 4; j++)
            crow[j] = acc[i][j] + bias[n0 + tx * 4 + j];
    }
}

// ---------------- row L2-normalize + ReLU (warp per row) -------------------
template <int W>
__global__ void norm_relu_kernel(float* __restrict__ h) {
    int gw = (blockIdx.x * blockDim.x + threadIdx.x) >> 5;
    int lane = threadIdx.x & 31;
    if (gw >= N_NODES) return;
    float* row = h + (size_t)gw * W;
    float v[W / 32];
    float ss = 0.f;
#pragma unroll
    for (int i = 0; i < W / 32; i++) {
        v[i] = row[lane + 32 * i];
        ss += v[i] * v[i];
    }
#pragma unroll
    for (int o = 16; o; o >>= 1) ss += __shfl_xor_sync(0xFFFFFFFFu, ss, o);
    float s = 1.0f / fmaxf(sqrtf(ss), 1e-12f);
#pragma unroll
    for (int i = 0; i < W / 32; i++)
        row[lane + 32 * i] = fmaxf(v[i] * s, 0.0f);
}

// ---------------- layer 3: K=128 -> 2 outputs, normalize, log_softmax ------
__global__ void layer3_kernel(const float* __restrict__ W3l,
                              const float* __restrict__ W3r,
                              const float* __restrict__ b3,
                              float* __restrict__ out) {
    int gw = (blockIdx.x * blockDim.x + threadIdx.x) >> 5;
    int lane = threadIdx.x & 31;
    if (gw >= N_NODES) return;
    float idg = g_invdeg[gw];
    const float* agg = g_agg + (size_t)gw * 128;
    const float* hh  = g_h2  + (size_t)gw * 128;
    float a0 = 0.f, a1 = 0.f;
#pragma unroll
    for (int k = lane; k < 128; k += 32) {
        float am = agg[k] * idg;
        float hv = hh[k];
        a0 += am * W3l[k]       + hv * W3r[k];
        a1 += am * W3l[128 + k] + hv * W3r[128 + k];
    }
#pragma unroll
    for (int o = 16; o; o >>= 1) {
        a0 += __shfl_xor_sync(0xFFFFFFFFu, a0, o);
        a1 += __shfl_xor_sync(0xFFFFFFFFu, a1, o);
    }
    if (lane == 0) {
        a0 += b3[0];
        a1 += b3[1];
        float n = sqrtf(a0 * a0 + a1 * a1);
        float s = 1.0f / fmaxf(n, 1e-12f);
        float v0 = a0 * s, v1 = a1 * s;
        float mx = fmaxf(v0, v1);
        float lse = mx + logf(expf(v0 - mx) + expf(v1 - mx));
        out[2 * gw + 0] = v0 - lse;
        out[2 * gw + 1] = v1 - lse;
    }
}

// ---------------- launch ----------------------------------------------------
extern "C" void kernel_launch(void* const* d_in, const int* in_sizes, int n_in,
                              void* d_out, int out_size) {
    const float* x   = (const float*)d_in[0];
    const void*  edg = d_in[1];
    const float* W1l = (const float*)d_in[2];
    const float* W1r = (const float*)d_in[3];
    const float* b1  = (const float*)d_in[4];
    const float* W2l = (const float*)d_in[5];
    const float* W2r = (const float*)d_in[6];
    const float* b2  = (const float*)d_in[7];
    const float* W3l = (const float*)d_in[8];
    const float* W3r = (const float*)d_in[9];
    const float* b3  = (const float*)d_in[10];
    float* out = (float*)d_out;

    void *aggp, *h1p, *h2p, *degp;
    cudaGetSymbolAddress(&aggp, g_agg);
    cudaGetSymbolAddress(&h1p,  g_h1);
    cudaGetSymbolAddress(&h2p,  g_h2);
    cudaGetSymbolAddress(&degp, g_deg);

    // dtype detection + degrees
    detect_kernel<<<1, 256>>>(edg);
    cudaMemsetAsync(degp, 0, (size_t)N_NODES * sizeof(int));
    count_kernel<<<(N_EDGES + 255) / 256, 256>>>(edg);
    invdeg_kernel<<<(N_NODES + 255) / 256, 256>>>();

    const int MB = (N_NODES + 63) / 64;  // 1563 GEMM m-blocks
    const int NORM_BLKS = (N_NODES * 32 + 255) / 256;

    // ---- Layer 1: agg(x) -> h1 = [agg|x] @ [W1l|W1r]^T + b1 ; norm+relu
    cudaMemsetAsync(aggp, 0, (size_t)N_NODES * 128 * sizeof(float));
    scatter_kernel<128><<<(N_EDGES * 32 + 255) / 256, 256>>>(edg, x);
    gemm_kernel<<<dim3(MB, 4), 256>>>((const float*)aggp, 128, x, 128,
                                      W1l, W1r, b1, (float*)h1p, 256);
    norm_relu_kernel<256><<<NORM_BLKS, 256>>>((float*)h1p);

    // ---- Layer 2: agg(h1) -> h2 = [agg|h1] @ [W2l|W2r]^T + b2 ; norm+relu
    cudaMemsetAsync(aggp, 0, (size_t)N_NODES * 256 * sizeof(float));
    scatter_kernel<256><<<(N_EDGES * 64 + 255) / 256, 256>>>(edg, (const float*)h1p);
    gemm_kernel<<<dim3(MB, 2), 256>>>((const float*)aggp, 256, (const float*)h1p, 256,
                                      W2l, W2r, b2, (float*)h2p, 128);
    norm_relu_kernel<128><<<NORM_BLKS, 256>>>((float*)h2p);

    // ---- Layer 3: agg(h2) -> 2-dim, normalize, log_softmax
    cudaMemsetAsync(aggp, 0, (size_t)N_NODES * 128 * sizeof(float));
    scatter_kernel<128><<<(N_EDGES * 32 + 255) / 256, 256>>>(edg, (const float*)h2p);
    layer3_kernel<<<NORM_BLKS, 256>>>(W3l, W3r, b3, out);
}

// round 2
// speedup vs baseline: 1.6140x; 1.6140x over previous
#include <cuda_runtime.h>
#include <math.h>

#define N_NODES 100000
#define N_EDGES 640000

// ---------------- scratch (device globals) ----------------------------------
__device__ float g_agg[(size_t)N_NODES * 128];
__device__ float g_h1 [(size_t)N_NODES * 256];
__device__ float g_t2 [(size_t)N_NODES * 256];   // [p2 | r2+b2]
__device__ float g_h2 [(size_t)N_NODES * 128];
__device__ float g_p3 [(size_t)N_NODES * 2];
__device__ float g_r3 [(size_t)N_NODES * 2];
__device__ int   g_deg[N_NODES];
__device__ int   g_rowptr[N_NODES + 1];
__device__ int   g_cursor[N_NODES];
__device__ int   g_csr[N_EDGES];
__device__ float g_Wp1[256 * 256];
__device__ float g_Wp2[256 * 256];
__device__ float g_bp2[256];
__device__ int   g_is64;

// ---------------- edge access (int32 or int64 layout) ----------------------
__device__ __forceinline__ int edge_at(const void* p, long long i) {
    if (g_is64) return (int)((const long long*)p)[i];
    return ((const int*)p)[i];
}

__global__ void detect_kernel(const void* edges) {
    __shared__ int nz;
    if (threadIdx.x == 0) nz = 0;
    __syncthreads();
    const int* p = (const int*)edges;
    for (int i = threadIdx.x; i < 1024; i += blockDim.x)
        if (p[2 * i + 1] != 0) atomicOr(&nz, 1);
    __syncthreads();
    if (threadIdx.x == 0) g_is64 = (nz == 0) ? 1 : 0;
}

__global__ void count_kernel(const void* edges) {
    int e = blockIdx.x * blockDim.x + threadIdx.x;
    if (e < N_EDGES) atomicAdd(&g_deg[edge_at(edges, (long long)N_EDGES + e)], 1);
}

// single-block exclusive scan of degrees -> row_ptr
__global__ void scan_kernel() {
    const int T = 1024;
    int t = threadIdx.x;
    const int per = (N_NODES + T - 1) / T;
    int s = t * per;
    int e = min(s + per, N_NODES);
    if (s > e) s = e;
    int sum = 0;
    for (int i = s; i < e; i++) sum += g_deg[i];
    __shared__ int sh[T];
    sh[t] = sum;
    __syncthreads();
    for (int off = 1; off < T; off <<= 1) {
        int v = (t >= off) ? sh[t - off] : 0;
        __syncthreads();
        sh[t] += v;
        __syncthreads();
    }
    int run = sh[t] - sum;  // exclusive prefix
    for (int i = s; i < e; i++) { g_rowptr[i] = run; run += g_deg[i]; }
    if (e == N_NODES) g_rowptr[N_NODES] = run;
}

__global__ void fill_kernel(const void* edges) {
    int e = blockIdx.x * blockDim.x + threadIdx.x;
    if (e >= N_EDGES) return;
    int s = edge_at(edges, e);
    int d = edge_at(edges, (long long)N_EDGES + e);
    int pos = g_rowptr[d] + atomicAdd(&g_cursor[d], 1);
    g_csr[pos] = s;
}

// pack weights: Wp1 row n = [W1l[n] | W1r[n]] (K-concat);
//               Wp2 rows 0-127 = W2l, 128-255 = W2r (N-concat); bp2 = [0|b2]
__global__ void pack_kernel(const float* __restrict__ W1l, const float* __restrict__ W1r,
                            const float* __restrict__ W2l, const float* __restrict__ W2r,
                            const float* __restrict__ b2) {
    int idx = blockIdx.x * blockDim.x + threadIdx.x;
    if (idx >= 65536) return;
    int n = idx >> 8, k = idx & 255;
    g_Wp1[idx] = (k < 128) ? W1l[n * 128 + k] : W1r[n * 128 + (k - 128)];
    g_Wp2[idx] = (n < 128) ? W2l[n * 256 + k] : W2r[(n - 128) * 256 + k];
    if (idx < 256) g_bp2[idx] = (idx < 128) ? 0.0f : b2[idx - 128];
}

// ---------------- CSR gather: agg[n] = mean over neighbors of feat[src] ----
// warp per node; 128 floats per row (lane owns float4); feat row stride param.
__global__ void gather_kernel(const float* __restrict__ feat, int stride) {
    int gw = (blockIdx.x * blockDim.x + threadIdx.x) >> 5;
    int lane = threadIdx.x & 31;
    if (gw >= N_NODES) return;
    int beg = g_rowptr[gw], end = g_rowptr[gw + 1];
    float4 acc = make_float4(0.f, 0.f, 0.f, 0.f);
    int j = beg;
    for (; j + 1 < end; j += 2) {
        int s0 = g_csr[j], s1 = g_csr[j + 1];
        float4 v0 = __ldg((const float4*)(feat + (size_t)s0 * stride + lane * 4));
        float4 v1 = __ldg((const float4*)(feat + (size_t)s1 * stride + lane * 4));
        acc.x += v0.x + v1.x; acc.y += v0.y + v1.y;
        acc.z += v0.z + v1.z; acc.w += v0.w + v1.w;
    }
    if (j < end) {
        int s0 = g_csr[j];
        float4 v0 = __ldg((const float4*)(feat + (size_t)s0 * stride + lane * 4));
        acc.x += v0.x; acc.y += v0.y; acc.z += v0.z; acc.w += v0.w;
    }
    float inv = 1.0f / (float)max(end - beg, 1);
    acc.x *= inv; acc.y *= inv; acc.z *= inv; acc.w *= inv;
    *(float4*)(g_agg + (size_t)gw * 128 + lane * 4) = acc;
}

// ---------------- SGEMM: C = concatK(A1,A2) @ W^T + bias -------------------
// 128x128x8 tiles, double-buffered, 8x8 per thread, 256 threads.
__global__ __launch_bounds__(256)
void sgemm_kernel(const float* __restrict__ A1, int K1,
                  const float* __restrict__ A2, int K2,
                  const float* __restrict__ W,
                  const float* __restrict__ bias,
                  float* __restrict__ C, int N) {
    const int BM = 128, BK = 8;
    __shared__ float As[2][BK][BM + 4];
    __shared__ float Bs[2][BK][BM + 4];

    int tid = threadIdx.x;
    int m0 = blockIdx.x * BM, n0 = blockIdx.y * BM;
    int lr = tid >> 1;            // 0..127
    int lk = (tid & 1) * 4;       // 0 or 4
    int arow = m0 + lr;
    int ty = tid >> 4, tx = tid & 15;
    int K = K1 + K2;
    int ntiles = K / BK;

    float acc[8][8];
#pragma unroll
    for (int i = 0; i < 8; i++)
#pragma unroll
        for (int jj = 0; jj < 8; jj++) acc[i][jj] = 0.f;

    float4 av, bv;
    // prologue: tile 0
    {
        int k = lk;
        av = make_float4(0.f, 0.f, 0.f, 0.f);
        if (arow < N_NODES) {
            if (k < K1) av = __ldg((const float4*)(A1 + (size_t)arow * K1 + k));
            else        av = __ldg((const float4*)(A2 + (size_t)arow * K2 + (k - K1)));
        }
        bv = __ldg((const float4*)(W + (size_t)(n0 + lr) * K + k));
        As[0][lk + 0][lr] = av.x; As[0][lk + 1][lr] = av.y;
        As[0][lk + 2][lr] = av.z; As[0][lk + 3][lr] = av.w;
        Bs[0][lk + 0][lr] = bv.x; Bs[0][lk + 1][lr] = bv.y;
        Bs[0][lk + 2][lr] = bv.z; Bs[0][lk + 3][lr] = bv.w;
    }
    __syncthreads();

    for (int kt = 0; kt < ntiles; kt++) {
        int cur = kt & 1;
        bool hasNext = (kt + 1 < ntiles);
        if (hasNext) {
            int k = (kt + 1) * BK + lk;
            av = make_float4(0.f, 0.f, 0.f, 0.f);
            if (arow < N_NODES) {
                if (k < K1) av = __ldg((const float4*)(A1 + (size_t)arow * K1 + k));
                else        av = __ldg((const float4*)(A2 + (size_t)arow * K2 + (k - K1)));
            }
            bv = __ldg((const float4*)(W + (size_t)(n0 + lr) * K + k));
        }
#pragma unroll
        for (int k = 0; k < BK; k++) {
            float a[8], b[8];
            *(float4*)(a)     = *(const float4*)&As[cur][k][ty * 8];
            *(float4*)(a + 4) = *(const float4*)&As[cur][k][ty * 8 + 4];
            *(float4*)(b)     = *(const float4*)&Bs[cur][k][tx * 8];
            *(float4*)(b + 4) = *(const float4*)&Bs[cur][k][tx * 8 + 4];
#pragma unroll
            for (int i = 0; i < 8; i++)
#pragma unroll
                for (int jj = 0; jj < 8; jj++) acc[i][jj] += a[i] * b[jj];
        }
        if (hasNext) {
            int nxt = cur ^ 1;
            As[nxt][lk + 0][lr] = av.x; As[nxt][lk + 1][lr] = av.y;
            As[nxt][lk + 2][lr] = av.z; As[nxt][lk + 3][lr] = av.w;
            Bs[nxt][lk + 0][lr] = bv.x; Bs[nxt][lk + 1][lr] = bv.y;
            Bs[nxt][lk + 2][lr] = bv.z; Bs[nxt][lk + 3][lr] = bv.w;
            __syncthreads();
        }
    }

    // epilogue
    float bvals[8];
#pragma unroll
    for (int jj = 0; jj < 8; jj++)
        bvals[jj] = bias ? __ldg(&bias[n0 + tx * 8 + jj]) : 0.0f;
#pragma unroll
    for (int i = 0; i < 8; i++) {
        int m = m0 + ty * 8 + i;
        if (m >= N_NODES) continue;
        float* cp = C + (size_t)m * N + n0 + tx * 8;
        float4 o0, o1;
        o0.x = acc[i][0] + bvals[0]; o0.y = acc[i][1] + bvals[1];
        o0.z = acc[i][2] + bvals[2]; o0.w = acc[i][3] + bvals[3];
        o1.x = acc[i][4] + bvals[4]; o1.y = acc[i][5] + bvals[5];
        o1.z = acc[i][6] + bvals[6]; o1.w = acc[i][7] + bvals[7];
        *(float4*)cp = o0;
        *(float4*)(cp + 4) = o1;
    }
}

// ---------------- row L2-normalize + ReLU (warp per row) -------------------
template <int W>
__global__ void norm_relu_kernel(float* __restrict__ h) {
    int gw = (blockIdx.x * blockDim.x + threadIdx.x) >> 5;
    int lane = threadIdx.x & 31;
    if (gw >= N_NODES) return;
    float* row = h + (size_t)gw * W;
    float v[W / 32];
    float ss = 0.f;
#pragma unroll
    for (int i = 0; i < W / 32; i++) {
        v[i] = row[lane + 32 * i];
        ss += v[i] * v[i];
    }
#pragma unroll
    for (int o = 16; o; o >>= 1) ss += __shfl_xor_sync(0xFFFFFFFFu, ss, o);
    float s = 1.0f / fmaxf(sqrtf(ss), 1e-12f);
#pragma unroll
    for (int i = 0; i < W / 32; i++)
        row[lane + 32 * i] = fmaxf(v[i] * s, 0.0f);
}

// ---------------- layer2 epilogue: h2 = normrelu(r2 + agg) -----------------
__global__ void norm2_kernel() {
    int gw = (blockIdx.x * blockDim.x + threadIdx.x) >> 5;
    int lane = threadIdx.x & 31;
    if (gw >= N_NODES) return;
    const float* r2 = g_t2 + (size_t)gw * 256 + 128;
    const float* ag = g_agg + (size_t)gw * 128;
    float4 u = __ldg((const float4*)(r2 + lane * 4));
    float4 a = *(const float4*)(ag + lane * 4);
    u.x += a.x; u.y += a.y; u.z += a.z; u.w += a.w;
    float ss = u.x * u.x + u.y * u.y + u.z * u.z + u.w * u.w;
#pragma unroll
    for (int o = 16; o; o >>= 1) ss += __shfl_xor_sync(0xFFFFFFFFu, ss, o);
    float s = 1.0f / fmaxf(sqrtf(ss), 1e-12f);
    u.x = fmaxf(u.x * s, 0.f); u.y = fmaxf(u.y * s, 0.f);
    u.z = fmaxf(u.z * s, 0.f); u.w = fmaxf(u.w * s, 0.f);
    *(float4*)(g_h2 + (size_t)gw * 128 + lane * 4) = u;
}

// ---------------- layer3: project h2 with W3l (->p3) and W3r (->r3) --------
__global__ void l3proj_kernel(const float* __restrict__ W3l,
                              const float* __restrict__ W3r) {
    int gw = (blockIdx.x * blockDim.x + threadIdx.x) >> 5;
    int lane = threadIdx.x & 31;
    if (gw >= N_NODES) return;
    const float* h = g_h2 + (size_t)gw * 128;
    float a0 = 0.f, a1 = 0.f, b0 = 0.f, b1 = 0.f;
#pragma unroll
    for (int k = lane; k < 128; k += 32) {
        float hv = h[k];
        a0 += hv * __ldg(&W3l[k]);
        a1 += hv * __ldg(&W3l[128 + k]);
        b0 += hv * __ldg(&W3r[k]);
        b1 += hv * __ldg(&W3r[128 + k]);
    }
#pragma unroll
    for (int o = 16; o; o >>= 1) {
        a0 += __shfl_xor_sync(0xFFFFFFFFu, a0, o);
        a1 += __shfl_xor_sync(0xFFFFFFFFu, a1, o);
        b0 += __shfl_xor_sync(0xFFFFFFFFu, b0, o);
        b1 += __shfl_xor_sync(0xFFFFFFFFu, b1, o);
    }
    if (lane == 0) {
        g_p3[2 * gw + 0] = a0; g_p3[2 * gw + 1] = a1;
        g_r3[2 * gw + 0] = b0; g_r3[2 * gw + 1] = b1;
    }
}

// gather 2-wide p3 + finalize (normalize + log_softmax); thread per node
__global__ void l3final_kernel(const float* __restrict__ b3,
                               float* __restrict__ out) {
    int n = blockIdx.x * blockDim.x + threadIdx.x;
    if (n >= N_NODES) return;
    int beg = g_rowptr[n], end = g_rowptr[n + 1];
    float s0 = 0.f, s1 = 0.f;
    for (int j = beg; j < end; j++) {
        int s = g_csr[j];
        float2 v = __ldg((const float2*)(g_p3 + 2 * (size_t)s));
        s0 += v.x; s1 += v.y;
    }
    float inv = 1.0f / (float)max(end - beg, 1);
    float v0 = s0 * inv + g_r3[2 * n + 0] + __ldg(&b3[0]);
    float v1 = s1 * inv + g_r3[2 * n + 1] + __ldg(&b3[1]);
    float nrm = sqrtf(v0 * v0 + v1 * v1);
    float sc = 1.0f / fmaxf(nrm, 1e-12f);
    v0 *= sc; v1 *= sc;
    float mx = fmaxf(v0, v1);
    float lse = mx + logf(expf(v0 - mx) + expf(v1 - mx));
    out[2 * n + 0] = v0 - lse;
    out[2 * n + 1] = v1 - lse;
}

// ---------------- launch ----------------------------------------------------
extern "C" void kernel_launch(void* const* d_in, const int* in_sizes, int n_in,
                              void* d_out, int out_size) {
    const float* x   = (const float*)d_in[0];
    const void*  edg = d_in[1];
    const float* W1l = (const float*)d_in[2];
    const float* W1r = (const float*)d_in[3];
    const float* b1  = (const float*)d_in[4];
    const float* W2l = (const float*)d_in[5];
    const float* W2r = (const float*)d_in[6];
    const float* b2  = (const float*)d_in[7];
    const float* W3l = (const float*)d_in[8];
    const float* W3r = (const float*)d_in[9];
    const float* b3  = (const float*)d_in[10];
    float* out = (float*)d_out;

    void *aggp, *h1p, *t2p, *degp, *curp, *wp1p, *wp2p, *bp2p;
    cudaGetSymbolAddress(&aggp, g_agg);
    cudaGetSymbolAddress(&h1p,  g_h1);
    cudaGetSymbolAddress(&t2p,  g_t2);
    cudaGetSymbolAddress(&degp, g_deg);
    cudaGetSymbolAddress(&curp, g_cursor);
    cudaGetSymbolAddress(&wp1p, g_Wp1);
    cudaGetSymbolAddress(&wp2p, g_Wp2);
    cudaGetSymbolAddress(&bp2p, g_bp2);

    const int EB = (N_EDGES + 255) / 256;
    const int WARP_BLKS = (N_NODES * 32 + 255) / 256;   // warp-per-node kernels
    const int MB = (N_NODES + 127) / 128;               // 782

    // CSR build + weight packing
    detect_kernel<<<1, 256>>>(edg);
    cudaMemsetAsync(degp, 0, (size_t)N_NODES * sizeof(int));
    cudaMemsetAsync(curp, 0, (size_t)N_NODES * sizeof(int));
    count_kernel<<<EB, 256>>>(edg);
    scan_kernel<<<1, 1024>>>();
    fill_kernel<<<EB, 256>>>(edg);
    pack_kernel<<<256, 256>>>(W1l, W1r, W2l, W2r, b2);

    // ---- Layer 1: agg = mean-gather(x); h1 = [agg|x]@Wp1^T + b1 ; norm+relu
    gather_kernel<<<WARP_BLKS, 256>>>(x, 128);
    sgemm_kernel<<<dim3(MB, 2), 256>>>((const float*)aggp, 128, x, 128,
                                       (const float*)wp1p, b1, (float*)h1p, 256);
    norm_relu_kernel<256><<<WARP_BLKS, 256>>>((float*)h1p);

    // ---- Layer 2: t2 = h1@[W2l;W2r]^T (+[0|b2]); agg = mean-gather(p2);
    //               h2 = normrelu(r2 + agg)
    sgemm_kernel<<<dim3(MB, 2), 256>>>((const float*)h1p, 256, (const float*)0, 0,
                                       (const float*)wp2p, (const float*)bp2p,
                                       (float*)t2p, 256);
    gather_kernel<<<WARP_BLKS, 256>>>((const float*)t2p, 256);
    norm2_kernel<<<WARP_BLKS, 256>>>();

    // ---- Layer 3: 2-wide projections, 2-wide gather, finalize
    l3proj_kernel<<<WARP_BLKS, 256>>>(W3l, W3r);
    l3final_kernel<<<(N_NODES + 255) / 256, 256>>>(b3, out);
}

// round 4
// speedup vs baseline: 2.7496x; 1.7036x over previous
#include <cuda_runtime.h>
#include <cuda_bf16.h>
#include <math.h>
#include <stdint.h>

#define N_NODES 100000
#define N_EDGES 640000

// ---------------- scratch (device globals) ----------------------------------
__device__ __nv_bfloat16 g_A1hi[(size_t)N_NODES * 256];
__device__ __nv_bfloat16 g_A1lo[(size_t)N_NODES * 256];
__device__ float g_c1 [(size_t)N_NODES * 256];
__device__ __nv_bfloat16 g_h1hi[(size_t)N_NODES * 256];
__device__ __nv_bfloat16 g_h1lo[(size_t)N_NODES * 256];
__device__ float g_p2 [(size_t)N_NODES * 128];
__device__ float g_r2b[(size_t)N_NODES * 128];
__device__ float g_h2 [(size_t)N_NODES * 128];
__device__ float g_p3 [(size_t)N_NODES * 2];
__device__ float g_r3 [(size_t)N_NODES * 2];
__device__ int   g_deg[N_NODES];
__device__ int   g_rowptr[N_NODES + 1];
__device__ int   g_cursor[N_NODES];
__device__ int   g_csr[N_EDGES];
__device__ __nv_bfloat16 g_W1p[256 * 768];   // [Whi|Wlo|Whi] K-concat, K-major
__device__ __nv_bfloat16 g_W2p[256 * 768];
__device__ float g_bp2[256];
__device__ int   g_is64;

__device__ __forceinline__ uint32_t smem_u32(const void* p) {
    uint32_t a;
    asm("{ .reg .u64 t; cvta.to.shared.u64 t, %1; cvt.u32.u64 %0, t; }"
        : "=r"(a) : "l"(p));
    return a;
}

__device__ __forceinline__ void bsplit(float v, __nv_bfloat16& hi, __nv_bfloat16& lo) {
    hi = __float2bfloat16(v);
    lo = __float2bfloat16(v - __bfloat162float(hi));
}

// ---------------- edge access / CSR build ----------------------------------
__device__ __forceinline__ int edge_at(const void* p, long long i) {
    if (g_is64) return (int)((const long long*)p)[i];
    return ((const int*)p)[i];
}

__global__ void detect_kernel(const void* edges) {
    __shared__ int nz;
    if (threadIdx.x == 0) nz = 0;
    __syncthreads();
    const int* p = (const int*)edges;
    for (int i = threadIdx.x; i < 1024; i += blockDim.x)
        if (p[2 * i + 1] != 0) atomicOr(&nz, 1);
    __syncthreads();
    if (threadIdx.x == 0) g_is64 = (nz == 0) ? 1 : 0;
}

__global__ void count_kernel(const void* edges) {
    int e = blockIdx.x * blockDim.x + threadIdx.x;
    if (e < N_EDGES) atomicAdd(&g_deg[edge_at(edges, (long long)N_EDGES + e)], 1);
}

__global__ void scan_kernel() {
    const int T = 1024;
    int t = threadIdx.x;
    const int per = (N_NODES + T - 1) / T;
    int s = t * per;
    int e = min(s + per, N_NODES);
    if (s > e) s = e;
    int sum = 0;
    for (int i = s; i < e; i++) sum += g_deg[i];
    __shared__ int sh[T];
    sh[t] = sum;
    __syncthreads();
    for (int off = 1; off < T; off <<= 1) {
        int v = (t >= off) ? sh[t - off] : 0;
        __syncthreads();
        sh[t] += v;
        __syncthreads();
    }
    int run = sh[t] - sum;
    for (int i = s; i < e; i++) { g_rowptr[i] = run; run += g_deg[i]; }
    if (e == N_NODES) g_rowptr[N_NODES] = run;
}

__global__ void fill_kernel(const void* edges) {
    int e = blockIdx.x * blockDim.x + threadIdx.x;
    if (e >= N_EDGES) return;
    int s = edge_at(edges, e);
    int d = edge_at(edges, (long long)N_EDGES + e);
    int pos = g_rowptr[d] + atomicAdd(&g_cursor[d], 1);
    g_csr[pos] = s;
}

// ---------------- weight packing (bf16 3-segment split) --------------------
__global__ void pack_kernel(const float* __restrict__ W1l, const float* __restrict__ W1r,
                            const float* __restrict__ W2l, const float* __restrict__ W2r,
                            const float* __restrict__ b2) {
    int idx = blockIdx.x * blockDim.x + threadIdx.x;
    if (idx >= 256 * 768) return;
    int n = idx / 768, k7 = idx % 768;
    int seg = k7 >> 8, k = k7 & 255;
    float v1 = (k < 128) ? W1l[n * 128 + k] : W1r[n * 128 + (k - 128)];
    float v2 = (n < 128) ? W2l[n * 256 + k] : W2r[(n - 128) * 256 + k];
    __nv_bfloat16 h1, l1, h2, l2;
    bsplit(v1, h1, l1);
    bsplit(v2, h2, l2);
    g_W1p[idx] = (seg == 1) ? l1 : h1;
    g_W2p[idx] = (seg == 1) ? l2 : h2;
    if (idx < 256) g_bp2[idx] = (idx < 128) ? 0.0f : b2[idx - 128];
}

// ---------------- x -> bf16 hi/lo into A1 cols 128-255 ---------------------
__global__ void convx_kernel(const float* __restrict__ x) {
    int t = blockIdx.x * blockDim.x + threadIdx.x;
    if (t >= N_NODES * 16) return;
    int row = t >> 4, col = (t & 15) * 8;
    const float* s = x + (size_t)row * 128 + col;
    size_t o = (size_t)row * 256 + 128 + col;
#pragma unroll
    for (int k = 0; k < 8; k += 2) {
        __nv_bfloat16 h0, l0, h1, l1;
        bsplit(s[k], h0, l0);
        bsplit(s[k + 1], h1, l1);
        __nv_bfloat162 hh; hh.x = h0; hh.y = h1;
        __nv_bfloat162 ll; ll.x = l0; ll.y = l1;
        *(__nv_bfloat162*)(g_A1hi + o + k) = hh;
        *(__nv_bfloat162*)(g_A1lo + o + k) = ll;
    }
}

// ---------------- gather1: mean of x -> bf16 hi/lo in A1 cols 0-127 --------
__global__ void gather1_kernel(const float* __restrict__ x) {
    int gw = (blockIdx.x * blockDim.x + threadIdx.x) >> 5;
    int lane = threadIdx.x & 31;
    if (gw >= N_NODES) return;
    int beg = g_rowptr[gw], end = g_rowptr[gw + 1];
    float4 acc = make_float4(0.f, 0.f, 0.f, 0.f);
    int j = beg;
    for (; j + 1 < end; j += 2) {
        int s0 = g_csr[j], s1 = g_csr[j + 1];
        float4 v0 = __ldg((const float4*)(x + (size_t)s0 * 128 + lane * 4));
        float4 v1 = __ldg((const float4*)(x + (size_t)s1 * 128 + lane * 4));
        acc.x += v0.x + v1.x; acc.y += v0.y + v1.y;
        acc.z += v0.z + v1.z; acc.w += v0.w + v1.w;
    }
    if (j < end) {
        int s0 = g_csr[j];
        float4 v0 = __ldg((const float4*)(x + (size_t)s0 * 128 + lane * 4));
        acc.x += v0.x; acc.y += v0.y; acc.z += v0.z; acc.w += v0.w;
    }
    float inv = 1.0f / (float)max(end - beg, 1);
    acc.x *= inv; acc.y *= inv; acc.z *= inv; acc.w *= inv;
    __nv_bfloat16 hx, lx, hy, ly, hz, lz, hw, lw;
    bsplit(acc.x, hx, lx); bsplit(acc.y, hy, ly);
    bsplit(acc.z, hz, lz); bsplit(acc.w, hw, lw);
    size_t o = (size_t)gw * 256 + lane * 4;
    __nv_bfloat162 t;
    t.x = hx; t.y = hy; *(__nv_bfloat162*)(g_A1hi + o) = t;
    t.x = hz; t.y = hw; *(__nv_bfloat162*)(g_A1hi + o + 2) = t;
    t.x = lx; t.y = ly; *(__nv_bfloat162*)(g_A1lo + o) = t;
    t.x = lz; t.y = lw; *(__nv_bfloat162*)(g_A1lo + o + 2) = t;
}

// ---------------- bf16 mma.sync GEMM: C[M,256] = A'[M,768] @ W'[256,768]^T --
// CTA tile 128x128, 8 warps (4x2), warp tile 32x64, BK=32, cp.async dbl-buf.
// blockIdx.y selects N-half; out pointer/ld per half (bias always packed 256).
#define SMEM_STRIDE 40   // bf16 elems per row (80B) — conflict-free ldmatrix
__global__ void __launch_bounds__(256)
gemm_mma(const __nv_bfloat16* __restrict__ Ahi, const __nv_bfloat16* __restrict__ Alo,
         const __nv_bfloat16* __restrict__ Wp, const float* __restrict__ bias,
         float* __restrict__ out0, float* __restrict__ out1, int ld0, int ld1)
{
    __shared__ __align__(16) __nv_bfloat16 Asb[2][128 * SMEM_STRIDE];
    __shared__ __align__(16) __nv_bfloat16 Bsb[2][128 * SMEM_STRIDE];
    __shared__ float sbias[128];

    const int tid = threadIdx.x;
    const int wid = tid >> 5, lane = tid & 31;
    const int m0 = blockIdx.x * 128;
    const int n0g = blockIdx.y * 128;
    const int mw = wid >> 1;      // 0..3
    const int nw = wid & 1;       // 0..1

    if (tid < 128) sbias[tid] = __ldg(&bias[n0g + tid]);

    const uint32_t As_base = smem_u32(Asb);
    const uint32_t Bs_base = smem_u32(Bsb);
    const uint32_t BUFB = 128 * SMEM_STRIDE * 2;   // bytes per buffer

    // per-thread 16B-chunk coords: chunk c = tid + i*256; row=c>>2, sub=c&3
    const int r0c = tid >> 2, sub0 = tid & 3;
    const int r1c = (tid + 256) >> 2, sub1 = (tid + 256) & 3;

#define LOAD_TILE(b, kt) do {                                                   \
    int k0 = (kt) * 32;                                                         \
    const __nv_bfloat16* Asrc = ((k0 >> 8) < 2) ? Ahi : Alo;                    \
    int kc = k0 & 255;                                                          \
    uint32_t Ad = As_base + (b) * BUFB;                                         \
    uint32_t Bd = Bs_base + (b) * BUFB;                                         \
    {                                                                           \
        int grow = m0 + r0c;                                                    \
        const void* src = Asrc + (size_t)grow * 256 + kc + sub0 * 8;            \
        int pb = (grow < N_NODES) ? 16 : 0;                                     \
        asm volatile("cp.async.cg.shared.global [%0], [%1], 16, %2;"            \
            :: "r"(Ad + r0c * 80 + sub0 * 16), "l"(src), "r"(pb));              \
        grow = m0 + r1c;                                                        \
        src = Asrc + (size_t)grow * 256 + kc + sub1 * 8;                        \
        pb = (grow < N_NODES) ? 16 : 0;                                         \
        asm volatile("cp.async.cg.shared.global [%0], [%1], 16, %2;"            \
            :: "r"(Ad + r1c * 80 + sub1 * 16), "l"(src), "r"(pb));              \
    }                                                                           \
    {                                                                           \
        const void* src = Wp + (size_t)(n0g + r0c) * 768 + k0 + sub0 * 8;       \
        asm volatile("cp.async.cg.shared.global [%0], [%1], 16;"                \
            :: "r"(Bd + r0c * 80 + sub0 * 16), "l"(src));                       \
        src = Wp + (size_t)(n0g + r1c) * 768 + k0 + sub1 * 8;                   \
        asm volatile("cp.async.cg.shared.global [%0], [%1], 16;"                \
            :: "r"(Bd + r1c * 80 + sub1 * 16), "l"(src));                       \
    }                                                                           \
    asm volatile("cp.async.commit_group;" ::: "memory");                        \
} while (0)

    float acc[2][8][4];
#pragma unroll
    for (int mt = 0; mt < 2; mt++)
#pragma unroll
        for (int nt = 0; nt < 8; nt++)
#pragma unroll
            for (int v = 0; v < 4; v++) acc[mt][nt][v] = 0.f;

    LOAD_TILE(0, 0);

    const int NK = 24;   // 768 / 32
    for (int kt = 0; kt < NK; kt++) {
        int b = kt & 1;
        if (kt + 1 < NK) {
            LOAD_TILE(b ^ 1, kt + 1);
            asm volatile("cp.async.wait_group 1;" ::: "memory");
        } else {
            asm volatile("cp.async.wait_group 0;" ::: "memory");
        }
        __syncthreads();

        uint32_t Au = As_base + b * BUFB;
        uint32_t Bu = Bs_base + b * BUFB;
#pragma unroll
        for (int kk = 0; kk < 32; kk += 16) {
            uint32_t a[2][4];
#pragma unroll
            for (int mt = 0; mt < 2; mt++) {
                uint32_t addr = Au + (mw * 32 + mt * 16 + (lane & 15)) * 80
                              + (kk + ((lane >> 4) << 3)) * 2;
                asm volatile("ldmatrix.sync.aligned.m8n8.x4.shared.b16 {%0,%1,%2,%3}, [%4];"
                    : "=r"(a[mt][0]), "=r"(a[mt][1]), "=r"(a[mt][2]), "=r"(a[mt][3])
                    : "r"(addr));
            }
            uint32_t bf[4][4];
#pragma unroll
            for (int nq = 0; nq < 4; nq++) {
                uint32_t addr = Bu + (nw * 64 + nq * 16 + (lane & 7) + ((lane >> 4) << 3)) * 80
                              + (kk + (((lane >> 3) & 1) << 3)) * 2;
                asm volatile("ldmatrix.sync.aligned.m8n8.x4.shared.b16 {%0,%1,%2,%3}, [%4];"
                    : "=r"(bf[nq][0]), "=r"(bf[nq][1]), "=r"(bf[nq][2]), "=r"(bf[nq][3])
                    : "r"(addr));
            }
#pragma unroll
            for (int mt = 0; mt < 2; mt++)
#pragma unroll
                for (int nt = 0; nt < 8; nt++) {
                    int nq = nt >> 1, hv = (nt & 1) << 1;
                    asm volatile(
                        "mma.sync.aligned.m16n8k16.row.col.f32.bf16.bf16.f32 "
                        "{%0,%1,%2,%3}, {%4,%5,%6,%7}, {%8,%9}, {%0,%1,%2,%3};"
                        : "+f"(acc[mt][nt][0]), "+f"(acc[mt][nt][1]),
                          "+f"(acc[mt][nt][2]), "+f"(acc[mt][nt][3])
                        : "r"(a[mt][0]), "r"(a[mt][1]), "r"(a[mt][2]), "r"(a[mt][3]),
                          "r"(bf[nq][hv]), "r"(bf[nq][hv + 1]));
                }
        }
        __syncthreads();
    }

    // epilogue
    float* o = (blockIdx.y == 0) ? out0 : out1;
    int ld = (blockIdx.y == 0) ? ld0 : ld1;
    int lr = lane >> 2, lc = (lane & 3) * 2;
#pragma unroll
    for (int mt = 0; mt < 2; mt++) {
        int ra = m0 + mw * 32 + mt * 16 + lr;
        int rb = ra + 8;
#pragma unroll
        for (int nt = 0; nt < 8; nt++) {
            int col = nw * 64 + nt * 8 + lc;
            float b0v = sbias[col], b1v = sbias[col + 1];
            if (ra < N_NODES) {
                float2 v; v.x = acc[mt][nt][0] + b0v; v.y = acc[mt][nt][1] + b1v;
                *(float2*)(o + (size_t)ra * ld + col) = v;
            }
            if (rb < N_NODES) {
                float2 v; v.x = acc[mt][nt][2] + b0v; v.y = acc[mt][nt][3] + b1v;
                *(float2*)(o + (size_t)rb * ld + col) = v;
            }
        }
    }
#undef LOAD_TILE
}

// ---------------- h1 = normrelu(c1) -> bf16 hi/lo ---------------------------
__global__ void norm_split_kernel(const float* __restrict__ C) {
    int gw = (blockIdx.x * blockDim.x + threadIdx.x) >> 5;
    int lane = threadIdx.x & 31;
    if (gw >= N_NODES) return;
    const float* row = C + (size_t)gw * 256;
    float4 v0 = __ldg((const float4*)(row + lane * 4));
    float4 v1 = __ldg((const float4*)(row + 128 + lane * 4));
    float ss = v0.x * v0.x + v0.y * v0.y + v0.z * v0.z + v0.w * v0.w
             + v1.x * v1.x + v1.y * v1.y + v1.z * v1.z + v1.w * v1.w;
#pragma unroll
    for (int o = 16; o; o >>= 1) ss += __shfl_xor_sync(0xFFFFFFFFu, ss, o);
    float s = 1.0f / fmaxf(sqrtf(ss), 1e-12f);
    float u[8] = { v0.x, v0.y, v0.z, v0.w, v1.x, v1.y, v1.z, v1.w };
#pragma unroll
    for (int i = 0; i < 8; i++) u[i] = fmaxf(u[i] * s, 0.f);
#pragma unroll
    for (int half = 0; half < 2; half++) {
        size_t o = (size_t)gw * 256 + half * 128 + lane * 4;
#pragma unroll
        for (int k = 0; k < 4; k += 2) {
            __nv_bfloat16 h0, l0, h1, l1;
            bsplit(u[half * 4 + k], h0, l0);
            bsplit(u[half * 4 + k + 1], h1, l1);
            __nv_bfloat162 hh; hh.x = h0; hh.y = h1;
            __nv_bfloat162 ll; ll.x = l0; ll.y = l1;
            *(__nv_bfloat162*)(g_h1hi + o + k) = hh;
            *(__nv_bfloat162*)(g_h1lo + o + k) = ll;
        }
    }
}

// ---------------- gather2 + norm2 fused: h2 = normrelu(mean(p2[nbr]) + r2b) -
__global__ void gather_norm2_kernel() {
    int gw = (blockIdx.x * blockDim.x + threadIdx.x) >> 5;
    int lane = threadIdx.x & 31;
    if (gw >= N_NODES) return;
    int beg = g_rowptr[gw], end = g_rowptr[gw + 1];
    float4 acc = make_float4(0.f, 0.f, 0.f, 0.f);
    int j = beg;
    for (; j + 1 < end; j += 2) {
        int s0 = g_csr[j], s1 = g_csr[j + 1];
        float4 v0 = __ldg((const float4*)(g_p2 + (size_t)s0 * 128 + lane * 4));
        float4 v1 = __ldg((const float4*)(g_p2 + (size_t)s1 * 128 + lane * 4));
        acc.x += v0.x + v1.x; acc.y += v0.y + v1.y;
        acc.z += v0.z + v1.z; acc.w += v0.w + v1.w;
    }
    if (j < end) {
        int s0 = g_csr[j];
        float4 v0 = __ldg((const float4*)(g_p2 + (size_t)s0 * 128 + lane * 4));
        acc.x += v0.x; acc.y += v0.y; acc.z += v0.z; acc.w += v0.w;
    }
    float inv = 1.0f / (float)max(end - beg, 1);
    float4 rb = *(const float4*)(g_r2b + (size_t)gw * 128 + lane * 4);
    float4 u;
    u.x = acc.x * inv + rb.x; u.y = acc.y * inv + rb.y;
    u.z = acc.z * inv + rb.z; u.w = acc.w * inv + rb.w;
    float ss = u.x * u.x + u.y * u.y + u.z * u.z + u.w * u.w;
#pragma unroll
    for (int o = 16; o; o >>= 1) ss += __shfl_xor_sync(0xFFFFFFFFu, ss, o);
    float s = 1.0f / fmaxf(sqrtf(ss), 1e-12f);
    u.x = fmaxf(u.x * s, 0.f); u.y = fmaxf(u.y * s, 0.f);
    u.z = fmaxf(u.z * s, 0.f); u.w = fmaxf(u.w * s, 0.f);
    *(float4*)(g_h2 + (size_t)gw * 128 + lane * 4) = u;
}

// ---------------- layer 3 ---------------------------------------------------
__global__ void l3proj_kernel(const float* __restrict__ W3l,
                              const float* __restrict__ W3r) {
    int gw = (blockIdx.x * blockDim.x + threadIdx.x) >> 5;
    int lane = threadIdx.x & 31;
    if (gw >= N_NODES) return;
    const float* h = g_h2 + (size_t)gw * 128;
    float a0 = 0.f, a1 = 0.f, b0 = 0.f, b1 = 0.f;
#pragma unroll
    for (int k = lane; k < 128; k += 32) {
        float hv = h[k];
        a0 += hv * __ldg(&W3l[k]);
        a1 += hv * __ldg(&W3l[128 + k]);
        b0 += hv * __ldg(&W3r[k]);
        b1 += hv * __ldg(&W3r[128 + k]);
    }
#pragma unroll
    for (int o = 16; o; o >>= 1) {
        a0 += __shfl_xor_sync(0xFFFFFFFFu, a0, o);
        a1 += __shfl_xor_sync(0xFFFFFFFFu, a1, o);
        b0 += __shfl_xor_sync(0xFFFFFFFFu, b0, o);
        b1 += __shfl_xor_sync(0xFFFFFFFFu, b1, o);
    }
    if (lane == 0) {
        g_p3[2 * gw + 0] = a0; g_p3[2 * gw + 1] = a1;
        g_r3[2 * gw + 0] = b0; g_r3[2 * gw + 1] = b1;
    }
}

__global__ void l3final_kernel(const float* __restrict__ b3,
                               float* __restrict__ out) {
    int n = blockIdx.x * blockDim.x + threadIdx.x;
    if (n >= N_NODES) return;
    int beg = g_rowptr[n], end = g_rowptr[n + 1];
    float s0 = 0.f, s1 = 0.f;
    for (int j = beg; j < end; j++) {
        int s = g_csr[j];
        float2 v = __ldg((const float2*)(g_p3 + 2 * (size_t)s));
        s0 += v.x; s1 += v.y;
    }
    float inv = 1.0f / (float)max(end - beg, 1);
    float v0 = s0 * inv + g_r3[2 * n + 0] + __ldg(&b3[0]);
    float v1 = s1 * inv + g_r3[2 * n + 1] + __ldg(&b3[1]);
    float nrm = sqrtf(v0 * v0 + v1 * v1);
    float sc = 1.0f / fmaxf(nrm, 1e-12f);
    v0 *= sc; v1 *= sc;
    float mx = fmaxf(v0, v1);
    float lse = mx + logf(expf(v0 - mx) + expf(v1 - mx));
    out[2 * n + 0] = v0 - lse;
    out[2 * n + 1] = v1 - lse;
}

// ---------------- launch ----------------------------------------------------
extern "C" void kernel_launch(void* const* d_in, const int* in_sizes, int n_in,
                              void* d_out, int out_size) {
    const float* x   = (const float*)d_in[0];
    const void*  edg = d_in[1];
    const float* W1l = (const float*)d_in[2];
    const float* W1r = (const float*)d_in[3];
    const float* b1  = (const float*)d_in[4];
    const float* W2l = (const float*)d_in[5];
    const float* W2r = (const float*)d_in[6];
    const float* b2  = (const float*)d_in[7];
    const float* W3l = (const float*)d_in[8];
    const float* W3r = (const float*)d_in[9];
    const float* b3  = (const float*)d_in[10];
    float* out = (float*)d_out;

    void *a1h, *a1l, *c1p, *h1h, *h1l, *p2p, *r2p, *w1p, *w2p, *bp2, *degp, *curp;
    cudaGetSymbolAddress(&a1h, g_A1hi);
    cudaGetSymbolAddress(&a1l, g_A1lo);
    cudaGetSymbolAddress(&c1p, g_c1);
    cudaGetSymbolAddress(&h1h, g_h1hi);
    cudaGetSymbolAddress(&h1l, g_h1lo);
    cudaGetSymbolAddress(&p2p, g_p2);
    cudaGetSymbolAddress(&r2p, g_r2b);
    cudaGetSymbolAddress(&w1p, g_W1p);
    cudaGetSymbolAddress(&w2p, g_W2p);
    cudaGetSymbolAddress(&bp2, g_bp2);
    cudaGetSymbolAddress(&degp, g_deg);
    cudaGetSymbolAddress(&curp, g_cursor);

    const int EB = (N_EDGES + 255) / 256;
    const int WARP_BLKS = (N_NODES * 32 + 255) / 256;
    const int MB = (N_NODES + 127) / 128;   // 782

    // CSR build + weight packing + x conversion
    detect_kernel<<<1, 256>>>(edg);
    cudaMemsetAsync(degp, 0, (size_t)N_NODES * sizeof(int));
    cudaMemsetAsync(curp, 0, (size_t)N_NODES * sizeof(int));
    count_kernel<<<EB, 256>>>(edg);
    scan_kernel<<<1, 1024>>>();
    fill_kernel<<<EB, 256>>>(edg);
    pack_kernel<<<768, 256>>>(W1l, W1r, W2l, W2r, b2);
    convx_kernel<<<(N_NODES * 16 + 255) / 256, 256>>>(x);

    // Layer 1: A' = [agg|x] split; c1 = A'@W1'^T + b1; h1 = normrelu(c1) split
    gather1_kernel<<<WARP_BLKS, 256>>>(x);
    gemm_mma<<<dim3(MB, 2), 256>>>((const __nv_bfloat16*)a1h, (const __nv_bfloat16*)a1l,
                                   (const __nv_bfloat16*)w1p, b1,
                                   (float*)c1p, (float*)c1p + 128, 256, 256);
    norm_split_kernel<<<WARP_BLKS, 256>>>((const float*)c1p);

    // Layer 2: [p2|r2b] = h1'@W2'^T + [0|b2]; h2 = normrelu(mean(p2[nbr]) + r2b)
    gemm_mma<<<dim3(MB, 2), 256>>>((const __nv_bfloat16*)h1h, (const __nv_bfloat16*)h1l,
                                   (const __nv_bfloat16*)w2p, (const float*)bp2,
                                   (float*)p2p, (float*)r2p, 128, 128);
    gather_norm2_kernel<<<WARP_BLKS, 256>>>();

    // Layer 3: 2-wide projections, 2-wide gather, finalize
    l3proj_kernel<<<WARP_BLKS, 256>>>(W3l, W3r);
    l3final_kernel<<<(N_NODES + 255) / 256, 256>>>(b3, out);
}